// round 1
// baseline (speedup 1.0000x reference)
#include <cuda_runtime.h>
#include <math.h>

// Problem constants
#define BB 2
#define NN 4096
#define DD 640
#define HH 8
#define DH 80
#define CN 77
#define CD 768
#define FF 2560           // GEGLU inner dim
#define MROWS (BB*NN)     // 8192
#define CROWS (BB*CN)     // 154

// ---------------- scratch (device globals: no allocation allowed) ----------------
__device__ float g_h   [MROWS*DD];
__device__ float g_q   [MROWS*DD];
__device__ float g_k   [MROWS*DD];
__device__ float g_v   [MROWS*DD];
__device__ float g_attn[MROWS*DD];
__device__ float g_x2  [MROWS*DD];
__device__ float g_x3  [MROWS*DD];
__device__ float g_proj[MROWS*2*FF];
__device__ float g_ffin[MROWS*FF];

// ---------------- LayerNorm: one block per row, D=640 ----------------
__global__ void ln_kernel(const float* __restrict__ x, const float* __restrict__ w,
                          const float* __restrict__ b, float* __restrict__ out)
{
    const int row = blockIdx.x;
    const float* xr = x + (size_t)row * DD;
    float s = 0.f, ss = 0.f;
    for (int c = threadIdx.x; c < DD; c += blockDim.x) {
        float v = xr[c]; s += v; ss += v * v;
    }
    __shared__ float red[64];
    #pragma unroll
    for (int m = 16; m; m >>= 1) {
        s  += __shfl_xor_sync(0xffffffffu, s,  m);
        ss += __shfl_xor_sync(0xffffffffu, ss, m);
    }
    const int wid = threadIdx.x >> 5;
    const int nw  = blockDim.x >> 5;
    if ((threadIdx.x & 31) == 0) { red[wid] = s; red[32 + wid] = ss; }
    __syncthreads();
    if (threadIdx.x < 32) {
        float s2  = (threadIdx.x < nw) ? red[threadIdx.x] : 0.f;
        float ss2 = (threadIdx.x < nw) ? red[32 + threadIdx.x] : 0.f;
        #pragma unroll
        for (int m = 16; m; m >>= 1) {
            s2  += __shfl_xor_sync(0xffffffffu, s2,  m);
            ss2 += __shfl_xor_sync(0xffffffffu, ss2, m);
        }
        if (threadIdx.x == 0) { red[0] = s2; red[1] = ss2; }
    }
    __syncthreads();
    const float mean = red[0] * (1.0f / DD);
    const float var  = red[1] * (1.0f / DD) - mean * mean;
    const float inv  = rsqrtf(var + 1e-5f);
    for (int c = threadIdx.x; c < DD; c += blockDim.x)
        out[(size_t)row * DD + c] = (xr[c] - mean) * inv * w[c] + b[c];
}

// ---------------- SGEMM: C[M,N] = A[M,K] @ W[K,N] (+bias) (+res) ----------------
// 128x128 block tile, KT=16, 256 threads, 8x8 micro-tile.
#define GBM 128
#define GBN 128
#define GBK 16
#define GPAD 132   // padded row length in smem (16B-aligned float4 rows)

__global__ __launch_bounds__(256, 2)
void gemm_kernel(const float* __restrict__ A, const float* __restrict__ W,
                 const float* __restrict__ bias, const float* __restrict__ res,
                 float* __restrict__ C, int M, int K, int Nn)
{
    __shared__ float As[GBK][GPAD];   // transposed: As[k][m]
    __shared__ float Bs[GBK][GPAD];   // natural:    Bs[k][n]
    const int tid = threadIdx.x;
    const int tx = tid & 15;          // 0..15 -> 8 output cols each
    const int ty = tid >> 4;          // 0..15 -> 8 output rows each
    const int m0 = blockIdx.y * GBM;
    const int n0 = blockIdx.x * GBN;

    float acc[8][8];
    #pragma unroll
    for (int i = 0; i < 8; i++)
        #pragma unroll
        for (int j = 0; j < 8; j++) acc[i][j] = 0.f;

    for (int kb = 0; kb < K; kb += GBK) {
        // load A tile (128 x 16) transposed
        #pragma unroll
        for (int l = 0; l < 2; l++) {
            int e = tid + l * 256;        // 0..511
            int row = e >> 2;             // 0..127
            int k4  = (e & 3) * 4;        // 0,4,8,12
            float4 v = make_float4(0.f, 0.f, 0.f, 0.f);
            if (m0 + row < M)
                v = *(const float4*)(A + (size_t)(m0 + row) * K + kb + k4);
            As[k4 + 0][row] = v.x; As[k4 + 1][row] = v.y;
            As[k4 + 2][row] = v.z; As[k4 + 3][row] = v.w;
        }
        // load B tile (16 x 128)
        #pragma unroll
        for (int l = 0; l < 2; l++) {
            int e = tid + l * 256;
            int kr = e >> 5;              // 0..15
            int nc = (e & 31) * 4;        // 0..124
            *(float4*)&Bs[kr][nc] = *(const float4*)(W + (size_t)(kb + kr) * Nn + n0 + nc);
        }
        __syncthreads();
        #pragma unroll
        for (int k = 0; k < GBK; k++) {
            float a[8], b[8];
            *(float4*)&a[0] = *(const float4*)&As[k][ty * 8];
            *(float4*)&a[4] = *(const float4*)&As[k][ty * 8 + 4];
            *(float4*)&b[0] = *(const float4*)&Bs[k][tx * 8];
            *(float4*)&b[4] = *(const float4*)&Bs[k][tx * 8 + 4];
            #pragma unroll
            for (int i = 0; i < 8; i++)
                #pragma unroll
                for (int j = 0; j < 8; j++) acc[i][j] = fmaf(a[i], b[j], acc[i][j]);
        }
        __syncthreads();
    }
    #pragma unroll
    for (int i = 0; i < 8; i++) {
        int m = m0 + ty * 8 + i;
        if (m >= M) continue;
        #pragma unroll
        for (int j = 0; j < 8; j++) {
            int n = n0 + tx * 8 + j;
            float v = acc[i][j];
            if (bias) v += bias[n];
            if (res)  v += res[(size_t)m * Nn + n];
            C[(size_t)m * Nn + n] = v;
        }
    }
}

// ---------------- Flash self-attention ----------------
// grid: (N/64, H, B), 256 threads. BM=BN=64, DH=80.
// smem: Qs[80][68], Ks[80][68] (d-major), Vs[64][80], Ps[64][68]
#define FPAD 68
#define FSMEM_FLOATS (80*FPAD*2 + 64*80 + 64*FPAD)

__global__ __launch_bounds__(256, 2)
void self_attn_kernel(const float* __restrict__ Q, const float* __restrict__ Kp,
                      const float* __restrict__ V, float* __restrict__ O)
{
    extern __shared__ float sm[];
    float* Qs = sm;                     // [80][68]
    float* Ks = Qs + 80 * FPAD;         // [80][68]
    float* Vs = Ks + 80 * FPAD;         // [64][80]
    float* Ps = Vs + 64 * 80;           // [64][68]

    const int tid = threadIdx.x;
    const int tx = tid & 15;            // key cols (4) / out cols (5)
    const int ty = tid >> 4;            // query rows (4)
    const int qb = blockIdx.x, h = blockIdx.y, b = blockIdx.z;
    const size_t base = (size_t)b * NN * DD + (size_t)h * DH;
    const float scale = 0.11180339887498949f;   // 1/sqrt(80)
    const int q0 = qb * 64;

    // load Q tile transposed + pre-scaled
    for (int e = tid; e < 64 * 80; e += 256) {
        int m = e / 80, d = e % 80;
        Qs[d * FPAD + m] = Q[base + (size_t)(q0 + m) * DD + d] * scale;
    }

    float acc[4][5];
    float mprev[4], lsum[4];
    #pragma unroll
    for (int i = 0; i < 4; i++) {
        mprev[i] = -3.0e38f; lsum[i] = 0.f;
        #pragma unroll
        for (int j = 0; j < 5; j++) acc[i][j] = 0.f;
    }

    for (int nb = 0; nb < NN / 64; nb++) {
        __syncthreads();   // prior Ps/Vs consumers done; also orders Qs writes (first iter)
        const int n0 = nb * 64;
        for (int e = tid; e < 64 * 80; e += 256) {
            int n = e / 80, d = e % 80;
            Ks[d * FPAD + n] = Kp[base + (size_t)(n0 + n) * DD + d];
            Vs[n * 80 + d]   = V [base + (size_t)(n0 + n) * DD + d];
        }
        __syncthreads();

        // S = (Q*scale) @ K^T, 64x64 tile, threads own 4x4
        float s[4][4];
        #pragma unroll
        for (int i = 0; i < 4; i++)
            #pragma unroll
            for (int j = 0; j < 4; j++) s[i][j] = 0.f;
        #pragma unroll 10
        for (int d = 0; d < 80; d++) {
            float a[4], bb[4];
            *(float4*)a  = *(const float4*)&Qs[d * FPAD + ty * 4];
            *(float4*)bb = *(const float4*)&Ks[d * FPAD + tx * 4];
            #pragma unroll
            for (int i = 0; i < 4; i++)
                #pragma unroll
                for (int j = 0; j < 4; j++) s[i][j] = fmaf(a[i], bb[j], s[i][j]);
        }

        // online softmax per row (16 threads share a row group; xor-shuffles stay in half)
        #pragma unroll
        for (int i = 0; i < 4; i++) {
            float mx = fmaxf(fmaxf(s[i][0], s[i][1]), fmaxf(s[i][2], s[i][3]));
            #pragma unroll
            for (int msk = 1; msk < 16; msk <<= 1)
                mx = fmaxf(mx, __shfl_xor_sync(0xffffffffu, mx, msk));
            float mnew  = fmaxf(mprev[i], mx);
            float alpha = __expf(mprev[i] - mnew);
            float rs = 0.f;
            #pragma unroll
            for (int j = 0; j < 4; j++) {
                float p = __expf(s[i][j] - mnew);
                Ps[(ty * 4 + i) * FPAD + tx * 4 + j] = p;
                rs += p;
            }
            #pragma unroll
            for (int msk = 1; msk < 16; msk <<= 1)
                rs += __shfl_xor_sync(0xffffffffu, rs, msk);
            lsum[i] = lsum[i] * alpha + rs;
            mprev[i] = mnew;
            #pragma unroll
            for (int j = 0; j < 5; j++) acc[i][j] *= alpha;
        }
        __syncthreads();

        // acc += P @ V  (out cols: tx*5..tx*5+4)
        #pragma unroll 8
        for (int kk = 0; kk < 64; kk++) {
            float vv[5];
            #pragma unroll
            for (int j = 0; j < 5; j++) vv[j] = Vs[kk * 80 + tx * 5 + j];
            #pragma unroll
            for (int i = 0; i < 4; i++) {
                float p = Ps[(ty * 4 + i) * FPAD + kk];
                #pragma unroll
                for (int j = 0; j < 5; j++) acc[i][j] = fmaf(p, vv[j], acc[i][j]);
            }
        }
    }

    #pragma unroll
    for (int i = 0; i < 4; i++) {
        float invl = 1.0f / lsum[i];
        #pragma unroll
        for (int j = 0; j < 5; j++)
            O[base + (size_t)(q0 + ty * 4 + i) * DD + tx * 5 + j] = acc[i][j] * invl;
    }
}

// ---------------- Cross-attention: K/V are tiny (77 tokens) ----------------
// grid: (N/64, H, B), 256 threads (8 warps), each warp handles 8 query rows.
#define XPAD 81
#define XSMEM_FLOATS (2*CN*XPAD + 8*80)

__global__ __launch_bounds__(256)
void cross_attn_kernel(const float* __restrict__ Q, const float* __restrict__ K2,
                       const float* __restrict__ V2, float* __restrict__ O)
{
    extern __shared__ float sm[];
    float* Ks = sm;                 // [77][81]
    float* Vs = Ks + CN * XPAD;     // [77][81]
    float* Ps = Vs + CN * XPAD;     // [8][80]

    const int tid = threadIdx.x, lane = tid & 31, w = tid >> 5;
    const int h = blockIdx.y, b = blockIdx.z;
    const float scale = 0.11180339887498949f;

    for (int e = tid; e < CN * 80; e += 256) {
        int n = e / 80, d = e % 80;
        Ks[n * XPAD + d] = K2[(size_t)(b * CN + n) * DD + h * DH + d];
        Vs[n * XPAD + d] = V2[(size_t)(b * CN + n) * DD + h * DH + d];
    }
    __syncthreads();

    const int row0 = blockIdx.x * 64;
    for (int r = w; r < 64; r += 8) {
        const int token = row0 + r;
        const float* qr = Q + ((size_t)b * NN + token) * DD + h * DH;

        const int k0 = lane, k1 = lane + 32, k2 = lane + 64;
        const bool v2ok = (k2 < CN);
        const float* ks0 = &Ks[k0 * XPAD];
        const float* ks1 = &Ks[k1 * XPAD];
        const float* ks2 = &Ks[(v2ok ? k2 : 0) * XPAD];
        float a0 = 0.f, a1 = 0.f, a2 = 0.f;
        #pragma unroll 10
        for (int d = 0; d < 80; d++) {
            float qd = __ldg(qr + d);     // broadcast, L1-cached
            a0 = fmaf(qd, ks0[d], a0);
            a1 = fmaf(qd, ks1[d], a1);
            a2 = fmaf(qd, ks2[d], a2);
        }
        float s0 = a0 * scale, s1 = a1 * scale;
        float s2 = v2ok ? (a2 * scale) : -3.0e38f;

        float mx = fmaxf(fmaxf(s0, s1), s2);
        #pragma unroll
        for (int m = 16; m; m >>= 1) mx = fmaxf(mx, __shfl_xor_sync(0xffffffffu, mx, m));
        float e0 = __expf(s0 - mx), e1 = __expf(s1 - mx);
        float e2 = v2ok ? __expf(s2 - mx) : 0.f;
        float sumv = e0 + e1 + e2;
        #pragma unroll
        for (int m = 16; m; m >>= 1) sumv += __shfl_xor_sync(0xffffffffu, sumv, m);
        float inv = 1.0f / sumv;
        Ps[w * 80 + k0] = e0 * inv;
        Ps[w * 80 + k1] = e1 * inv;
        if (v2ok) Ps[w * 80 + k2] = e2 * inv;
        __syncwarp();

        #pragma unroll
        for (int c = lane; c < 80; c += 32) {
            float o = 0.f;
            for (int j = 0; j < CN; j++)
                o = fmaf(Ps[w * 80 + j], Vs[j * XPAD + c], o);
            O[((size_t)b * NN + token) * DD + h * DH + c] = o;
        }
        __syncwarp();
    }
}

// ---------------- GEGLU: out = a * gelu_exact(g) ----------------
__global__ void geglu_kernel(const float* __restrict__ proj, float* __restrict__ out)
{
    int idx = blockIdx.x * blockDim.x + threadIdx.x;
    if (idx >= MROWS * FF) return;
    int row = idx / FF, c = idx % FF;
    float a = proj[(size_t)row * (2 * FF) + c];
    float g = proj[(size_t)row * (2 * FF) + FF + c];
    float gelu = 0.5f * g * (1.0f + erff(g * 0.70710678118654752f));
    out[idx] = a * gelu;
}

// ---------------- host launch ----------------
static void launch_gemm(const float* A, const float* W, const float* bias,
                        const float* res, float* C, int M, int K, int Nn)
{
    dim3 grid(Nn / GBN, (M + GBM - 1) / GBM);
    gemm_kernel<<<grid, 256>>>(A, W, bias, res, C, M, K, Nn);
}

extern "C" void kernel_launch(void* const* d_in, const int* in_sizes, int n_in,
                              void* d_out, int out_size)
{
    (void)in_sizes; (void)n_in; (void)out_size;
    const float* x     = (const float*)d_in[0];
    const float* ctx   = (const float*)d_in[1];
    const float* ln1_w = (const float*)d_in[2];
    const float* ln1_b = (const float*)d_in[3];
    const float* ln2_w = (const float*)d_in[4];
    const float* ln2_b = (const float*)d_in[5];
    const float* ln3_w = (const float*)d_in[6];
    const float* ln3_b = (const float*)d_in[7];
    const float* wq1   = (const float*)d_in[8];
    const float* wk1   = (const float*)d_in[9];
    const float* wv1   = (const float*)d_in[10];
    const float* wo1   = (const float*)d_in[11];
    const float* bo1   = (const float*)d_in[12];
    const float* wq2   = (const float*)d_in[13];
    const float* wk2   = (const float*)d_in[14];
    const float* wv2   = (const float*)d_in[15];
    const float* wo2   = (const float*)d_in[16];
    const float* bo2   = (const float*)d_in[17];
    const float* wff1  = (const float*)d_in[18];
    const float* bff1  = (const float*)d_in[19];
    const float* wff2  = (const float*)d_in[20];
    const float* bff2  = (const float*)d_in[21];
    float* out = (float*)d_out;

    float *h, *q, *k, *v, *attn, *x2, *x3, *proj, *ffin;
    cudaGetSymbolAddress((void**)&h,    g_h);
    cudaGetSymbolAddress((void**)&q,    g_q);
    cudaGetSymbolAddress((void**)&k,    g_k);
    cudaGetSymbolAddress((void**)&v,    g_v);
    cudaGetSymbolAddress((void**)&attn, g_attn);
    cudaGetSymbolAddress((void**)&x2,   g_x2);
    cudaGetSymbolAddress((void**)&x3,   g_x3);
    cudaGetSymbolAddress((void**)&proj, g_proj);
    cudaGetSymbolAddress((void**)&ffin, g_ffin);

    cudaFuncSetAttribute(self_attn_kernel, cudaFuncAttributeMaxDynamicSharedMemorySize,
                         FSMEM_FLOATS * (int)sizeof(float));
    cudaFuncSetAttribute(cross_attn_kernel, cudaFuncAttributeMaxDynamicSharedMemorySize,
                         XSMEM_FLOATS * (int)sizeof(float));

    // ---- Block 1: self-attention ----
    ln_kernel<<<MROWS, 256>>>(x, ln1_w, ln1_b, h);
    launch_gemm(h, wq1, nullptr, nullptr, q, MROWS, DD, DD);
    launch_gemm(h, wk1, nullptr, nullptr, k, MROWS, DD, DD);
    launch_gemm(h, wv1, nullptr, nullptr, v, MROWS, DD, DD);
    {
        dim3 grid(NN / 64, HH, BB);
        self_attn_kernel<<<grid, 256, FSMEM_FLOATS * sizeof(float)>>>(q, k, v, attn);
    }
    launch_gemm(attn, wo1, bo1, x, x2, MROWS, DD, DD);

    // ---- Block 2: cross-attention ----
    ln_kernel<<<MROWS, 256>>>(x2, ln2_w, ln2_b, h);
    launch_gemm(h,   wq2, nullptr, nullptr, q, MROWS, DD, DD);
    launch_gemm(ctx, wk2, nullptr, nullptr, k, CROWS, CD, DD);
    launch_gemm(ctx, wv2, nullptr, nullptr, v, CROWS, CD, DD);
    {
        dim3 grid(NN / 64, HH, BB);
        cross_attn_kernel<<<grid, 256, XSMEM_FLOATS * sizeof(float)>>>(q, k, v, attn);
    }
    launch_gemm(attn, wo2, bo2, x2, x3, MROWS, DD, DD);

    // ---- Block 3: GEGLU FFN ----
    ln_kernel<<<MROWS, 256>>>(x3, ln3_w, ln3_b, h);
    launch_gemm(h, wff1, bff1, nullptr, proj, MROWS, DD, 2 * FF);
    {
        int tot = MROWS * FF;
        geglu_kernel<<<(tot + 255) / 256, 256>>>(proj, ffin);
    }
    launch_gemm(ffin, wff2, bff2, x3, out, MROWS, FF, DD);
}

// round 7
// speedup vs baseline: 1.9279x; 1.9279x over previous
#include <cuda_runtime.h>
#include <math.h>

// Problem constants
#define BB 2
#define NN 4096
#define DD 640
#define HH 8
#define DH 80
#define CN 77
#define CD 768
#define FF 2560           // GEGLU inner dim
#define MROWS (BB*NN)     // 8192
#define CROWS (BB*CN)     // 154

// ---------------- scratch ----------------
__device__ float g_h   [MROWS*DD];
__device__ float g_q   [MROWS*DD];
__device__ float g_k   [MROWS*DD];
__device__ float g_v   [MROWS*DD];
__device__ float g_attn[MROWS*DD];
__device__ float g_x2  [MROWS*DD];
__device__ float g_x3  [MROWS*DD];
__device__ float g_proj[MROWS*2*FF];
__device__ float g_ffin[MROWS*FF];

// ---------------- LayerNorm (float4-vectorized; D=640 = 160 float4) ----------------
__global__ void ln_kernel(const float* __restrict__ x, const float* __restrict__ w,
                          const float* __restrict__ b, float* __restrict__ out)
{
    const int row = blockIdx.x;
    const float4* xr4 = (const float4*)(x + (size_t)row * DD);
    float s = 0.f, ss = 0.f;
    for (int c = threadIdx.x; c < DD / 4; c += blockDim.x) {
        float4 v = xr4[c];
        s  += v.x + v.y + v.z + v.w;
        ss += v.x * v.x + v.y * v.y + v.z * v.z + v.w * v.w;
    }
    __shared__ float red[64];
    #pragma unroll
    for (int m = 16; m; m >>= 1) {
        s  += __shfl_xor_sync(0xffffffffu, s,  m);
        ss += __shfl_xor_sync(0xffffffffu, ss, m);
    }
    const int wid = threadIdx.x >> 5;
    const int nw  = blockDim.x >> 5;
    if ((threadIdx.x & 31) == 0) { red[wid] = s; red[32 + wid] = ss; }
    __syncthreads();
    if (threadIdx.x < 32) {
        float s2  = (threadIdx.x < nw) ? red[threadIdx.x] : 0.f;
        float ss2 = (threadIdx.x < nw) ? red[32 + threadIdx.x] : 0.f;
        #pragma unroll
        for (int m = 16; m; m >>= 1) {
            s2  += __shfl_xor_sync(0xffffffffu, s2,  m);
            ss2 += __shfl_xor_sync(0xffffffffu, ss2, m);
        }
        if (threadIdx.x == 0) { red[0] = s2; red[1] = ss2; }
    }
    __syncthreads();
    const float mean = red[0] * (1.0f / DD);
    const float var  = red[1] * (1.0f / DD) - mean * mean;
    const float inv  = rsqrtf(var + 1e-5f);
    float4* out4 = (float4*)(out + (size_t)row * DD);
    const float4* w4 = (const float4*)w;
    const float4* b4 = (const float4*)b;
    for (int c = threadIdx.x; c < DD / 4; c += blockDim.x) {
        float4 v = xr4[c], wv = w4[c], bv = b4[c];
        v.x = (v.x - mean) * inv * wv.x + bv.x;
        v.y = (v.y - mean) * inv * wv.y + bv.y;
        v.z = (v.z - mean) * inv * wv.z + bv.z;
        v.w = (v.w - mean) * inv * wv.w + bv.w;
        out4[c] = v;
    }
}

// ---------------- tf32 helpers ----------------
__device__ __forceinline__ float f2tf(float f) {
    unsigned u;
    asm("cvt.rna.tf32.f32 %0, %1;" : "=r"(u) : "f"(f));
    return __uint_as_float(u);
}

__device__ __forceinline__ void mma_tf32(float c[4], const unsigned a[4], const unsigned b[2]) {
    asm volatile(
        "mma.sync.aligned.m16n8k8.row.col.f32.tf32.tf32.f32 "
        "{%0,%1,%2,%3}, {%4,%5,%6,%7}, {%8,%9}, {%0,%1,%2,%3};\n"
        : "+f"(c[0]), "+f"(c[1]), "+f"(c[2]), "+f"(c[3])
        : "r"(a[0]), "r"(a[1]), "r"(a[2]), "r"(a[3]), "r"(b[0]), "r"(b[1]));
}

// 16-byte cp.async with zero-fill when invalid (src-size 0)
__device__ __forceinline__ void cp16(float* dst_smem, const float* src_gmem, bool valid) {
    unsigned sdst = (unsigned)__cvta_generic_to_shared(dst_smem);
    int sz = valid ? 16 : 0;
    asm volatile("cp.async.cg.shared.global [%0], [%1], 16, %2;\n"
                 :: "r"(sdst), "l"(src_gmem), "r"(sz) : "memory");
}
__device__ __forceinline__ void cp_commit() {
    asm volatile("cp.async.commit_group;\n" ::: "memory");
}
__device__ __forceinline__ void cp_wait0() {
    asm volatile("cp.async.wait_group 0;\n" ::: "memory");
}

// ---------------- tf32 tensor-core GEMM, cp.async double-buffered ----------------
// BM=128, BK=32, BN_ in {128,64}. 256 threads (8 warps). Dynamic smem.
template<int BN_>
__global__ __launch_bounds__(256, 2)
void mma_gemm_kernel(const float* __restrict__ A, const float* __restrict__ W,
                     const float* __restrict__ bias, const float* __restrict__ res,
                     float* __restrict__ C, int M, int K, int Nn)
{
    constexpr int BM = 128, BK = 32;
    constexpr int WM = (BN_ == 128) ? 64 : 32;
    constexpr int MF = WM / 16;
    constexpr int NF = 4;
    constexpr int ASTR = BK + 4;
    constexpr int BSTR = BN_ + 8;
    constexpr int ASZ = BM * ASTR;
    constexpr int BSZ = BK * BSTR;

    extern __shared__ float sm[];
    float* Asb[2] = { sm, sm + ASZ };
    float* Bsb[2] = { sm + 2 * ASZ, sm + 2 * ASZ + BSZ };

    const int tid  = threadIdx.x;
    const int lane = tid & 31;
    const int w    = tid >> 5;
    const int wm   = (BN_ == 128) ? (w >> 2) : (w >> 1);
    const int wn   = (BN_ == 128) ? (w & 3)  : (w & 1);
    const int m0   = blockIdx.y * BM;
    const int n0   = blockIdx.x * BN_;
    const int gid  = lane >> 2;
    const int tig  = lane & 3;
    const int nk   = K / BK;

    float acc[MF][NF][4];
    #pragma unroll
    for (int i = 0; i < MF; i++)
        #pragma unroll
        for (int j = 0; j < NF; j++)
            #pragma unroll
            for (int r = 0; r < 4; r++) acc[i][j][r] = 0.f;

    auto prefetch = [&](int kb, int bufi) {
        const int kbase = kb * BK;
        #pragma unroll
        for (int i = 0; i < 4; i++) {
            int e   = tid + i * 256;
            int row = e >> 3;
            int col = (e & 7) * 4;
            cp16(&Asb[bufi][row * ASTR + col],
                 A + (size_t)(m0 + row) * K + kbase + col,
                 (m0 + row) < M);
        }
        #pragma unroll
        for (int i = 0; i < (BK * BN_) / (256 * 4); i++) {
            int e = tid + i * 256;
            int k = e / (BN_ / 4);
            int c = (e % (BN_ / 4)) * 4;
            cp16(&Bsb[bufi][k * BSTR + c],
                 W + (size_t)(kbase + k) * Nn + n0 + c, true);
        }
        cp_commit();
    };

    prefetch(0, 0);

    for (int kb = 0; kb < nk; kb++) {
        cp_wait0();
        __syncthreads();
        if (kb + 1 < nk) prefetch(kb + 1, (kb + 1) & 1);

        const float* As = Asb[kb & 1];
        const float* Bs = Bsb[kb & 1];

        #pragma unroll
        for (int ks = 0; ks < BK / 8; ks++) {
            unsigned afr[MF][4], bfr[NF][2];
            #pragma unroll
            for (int fm = 0; fm < MF; fm++) {
                const int rbase = wm * WM + fm * 16;
                afr[fm][0] = __float_as_uint(As[(rbase + gid)     * ASTR + ks * 8 + tig]);
                afr[fm][1] = __float_as_uint(As[(rbase + gid + 8) * ASTR + ks * 8 + tig]);
                afr[fm][2] = __float_as_uint(As[(rbase + gid)     * ASTR + ks * 8 + tig + 4]);
                afr[fm][3] = __float_as_uint(As[(rbase + gid + 8) * ASTR + ks * 8 + tig + 4]);
            }
            #pragma unroll
            for (int fn = 0; fn < NF; fn++) {
                const int cb = wn * 32 + fn * 8;
                bfr[fn][0] = __float_as_uint(Bs[(ks * 8 + tig)     * BSTR + cb + gid]);
                bfr[fn][1] = __float_as_uint(Bs[(ks * 8 + tig + 4) * BSTR + cb + gid]);
            }
            #pragma unroll
            for (int fm = 0; fm < MF; fm++)
                #pragma unroll
                for (int fn = 0; fn < NF; fn++)
                    mma_tf32(acc[fm][fn], afr[fm], bfr[fn]);
        }
    }

    #pragma unroll
    for (int fm = 0; fm < MF; fm++) {
        const int r0 = m0 + wm * WM + fm * 16 + gid;
        const int r1 = r0 + 8;
        #pragma unroll
        for (int fn = 0; fn < NF; fn++) {
            const int c = n0 + wn * 32 + fn * 8 + tig * 2;
            float2 o0 = make_float2(acc[fm][fn][0], acc[fm][fn][1]);
            float2 o1 = make_float2(acc[fm][fn][2], acc[fm][fn][3]);
            if (bias) {
                o0.x += bias[c]; o0.y += bias[c + 1];
                o1.x += bias[c]; o1.y += bias[c + 1];
            }
            if (r0 < M) {
                if (res) {
                    float2 rr = *(const float2*)(res + (size_t)r0 * Nn + c);
                    o0.x += rr.x; o0.y += rr.y;
                }
                *(float2*)(C + (size_t)r0 * Nn + c) = o0;
            }
            if (r1 < M) {
                if (res) {
                    float2 rr = *(const float2*)(res + (size_t)r1 * Nn + c);
                    o1.x += rr.x; o1.y += rr.y;
                }
                *(float2*)(C + (size_t)r1 * Nn + c) = o1;
            }
        }
    }
}

// ---------------- Flash self-attention, tf32 tensor cores ----------------
#define QSTR 84
#define KSTR 84
#define VSTR 88
#define PSTR 68
#define ASMEM_FLOATS (64*QSTR + 64*KSTR + 64*VSTR + 64*PSTR)

__global__ __launch_bounds__(128)
void self_attn_tc_kernel(const float* __restrict__ Q, const float* __restrict__ Kp,
                         const float* __restrict__ V, float* __restrict__ O)
{
    extern __shared__ float sm[];
    float* Qs = sm;                 // [64][QSTR]
    float* Ks = Qs + 64 * QSTR;     // [64][KSTR]
    float* Vs = Ks + 64 * KSTR;     // [64][VSTR]
    float* Ps = Vs + 64 * VSTR;     // [64][PSTR]

    const int tid = threadIdx.x, lane = tid & 31, w = tid >> 5;
    const int gid = lane >> 2, tig = lane & 3;
    const int qb = blockIdx.x, h = blockIdx.y, b = blockIdx.z;
    const size_t base = (size_t)b * NN * DD + (size_t)h * DH;
    const int q0 = qb * 64;
    const float scale = 0.11180339887498949f;   // 1/sqrt(80)

    for (int e = tid; e < 64 * 80; e += 128) {
        int m = e / 80, d = e % 80;
        Qs[m * QSTR + d] = f2tf(Q[base + (size_t)(q0 + m) * DD + d] * scale);
    }

    float o[10][4];
    #pragma unroll
    for (int fn = 0; fn < 10; fn++)
        #pragma unroll
        for (int r = 0; r < 4; r++) o[fn][r] = 0.f;
    float mprev0 = -1e30f, mprev1 = -1e30f, lsum0 = 0.f, lsum1 = 0.f;

    const int rlo = w * 16 + gid;
    for (int nb = 0; nb < NN / 64; nb++) {
        __syncthreads();
        const int n0g = nb * 64;
        for (int e = tid; e < 64 * 80; e += 128) {
            int n = e / 80, d = e % 80;
            Ks[n * KSTR + d] = f2tf(Kp[base + (size_t)(n0g + n) * DD + d]);
            Vs[n * VSTR + d] = f2tf(V [base + (size_t)(n0g + n) * DD + d]);
        }
        __syncthreads();

        float s[8][4];
        #pragma unroll
        for (int fn = 0; fn < 8; fn++)
            #pragma unroll
            for (int r = 0; r < 4; r++) s[fn][r] = 0.f;
        #pragma unroll
        for (int kk = 0; kk < 10; kk++) {
            unsigned a[4];
            const int ar = rlo * QSTR + kk * 8;
            a[0] = __float_as_uint(Qs[ar + tig]);
            a[1] = __float_as_uint(Qs[ar + 8 * QSTR + tig]);
            a[2] = __float_as_uint(Qs[ar + tig + 4]);
            a[3] = __float_as_uint(Qs[ar + 8 * QSTR + tig + 4]);
            #pragma unroll
            for (int fn = 0; fn < 8; fn++) {
                unsigned bf[2];
                const int br = (fn * 8 + gid) * KSTR + kk * 8;
                bf[0] = __float_as_uint(Ks[br + tig]);
                bf[1] = __float_as_uint(Ks[br + tig + 4]);
                mma_tf32(s[fn], a, bf);
            }
        }

        float mx0 = -1e30f, mx1 = -1e30f;
        #pragma unroll
        for (int fn = 0; fn < 8; fn++) {
            mx0 = fmaxf(mx0, fmaxf(s[fn][0], s[fn][1]));
            mx1 = fmaxf(mx1, fmaxf(s[fn][2], s[fn][3]));
        }
        mx0 = fmaxf(mx0, __shfl_xor_sync(0xffffffffu, mx0, 1));
        mx0 = fmaxf(mx0, __shfl_xor_sync(0xffffffffu, mx0, 2));
        mx1 = fmaxf(mx1, __shfl_xor_sync(0xffffffffu, mx1, 1));
        mx1 = fmaxf(mx1, __shfl_xor_sync(0xffffffffu, mx1, 2));
        const float mnew0 = fmaxf(mprev0, mx0);
        const float mnew1 = fmaxf(mprev1, mx1);
        const float alpha0 = __expf(mprev0 - mnew0);
        const float alpha1 = __expf(mprev1 - mnew1);
        float rs0 = 0.f, rs1 = 0.f;
        #pragma unroll
        for (int fn = 0; fn < 8; fn++) {
            s[fn][0] = __expf(s[fn][0] - mnew0);
            s[fn][1] = __expf(s[fn][1] - mnew0);
            s[fn][2] = __expf(s[fn][2] - mnew1);
            s[fn][3] = __expf(s[fn][3] - mnew1);
            rs0 += s[fn][0] + s[fn][1];
            rs1 += s[fn][2] + s[fn][3];
        }
        rs0 += __shfl_xor_sync(0xffffffffu, rs0, 1);
        rs0 += __shfl_xor_sync(0xffffffffu, rs0, 2);
        rs1 += __shfl_xor_sync(0xffffffffu, rs1, 1);
        rs1 += __shfl_xor_sync(0xffffffffu, rs1, 2);
        lsum0 = lsum0 * alpha0 + rs0;
        lsum1 = lsum1 * alpha1 + rs1;
        mprev0 = mnew0; mprev1 = mnew1;
        #pragma unroll
        for (int fn = 0; fn < 10; fn++) {
            o[fn][0] *= alpha0; o[fn][1] *= alpha0;
            o[fn][2] *= alpha1; o[fn][3] *= alpha1;
        }

        #pragma unroll
        for (int fn = 0; fn < 8; fn++) {
            float2 p0 = make_float2(f2tf(s[fn][0]), f2tf(s[fn][1]));
            float2 p1 = make_float2(f2tf(s[fn][2]), f2tf(s[fn][3]));
            *(float2*)&Ps[rlo * PSTR + fn * 8 + 2 * tig]       = p0;
            *(float2*)&Ps[(rlo + 8) * PSTR + fn * 8 + 2 * tig] = p1;
        }
        __syncwarp();

        #pragma unroll
        for (int kk = 0; kk < 8; kk++) {
            unsigned a[4];
            const int pr = rlo * PSTR + kk * 8;
            a[0] = __float_as_uint(Ps[pr + tig]);
            a[1] = __float_as_uint(Ps[pr + 8 * PSTR + tig]);
            a[2] = __float_as_uint(Ps[pr + tig + 4]);
            a[3] = __float_as_uint(Ps[pr + 8 * PSTR + tig + 4]);
            #pragma unroll
            for (int fn = 0; fn < 10; fn++) {
                unsigned bf[2];
                const int vr = (kk * 8 + tig) * VSTR + fn * 8 + gid;
                bf[0] = __float_as_uint(Vs[vr]);
                bf[1] = __float_as_uint(Vs[vr + 4 * VSTR]);
                mma_tf32(o[fn], a, bf);
            }
        }
        __syncwarp();
    }

    const float inv0 = 1.0f / lsum0;
    const float inv1 = 1.0f / lsum1;
    #pragma unroll
    for (int fn = 0; fn < 10; fn++) {
        const int c = fn * 8 + 2 * tig;
        float2 o0 = make_float2(o[fn][0] * inv0, o[fn][1] * inv0);
        float2 o1 = make_float2(o[fn][2] * inv1, o[fn][3] * inv1);
        *(float2*)(O + base + (size_t)(q0 + rlo) * DD + c)     = o0;
        *(float2*)(O + base + (size_t)(q0 + rlo + 8) * DD + c) = o1;
    }
}

// ---------------- Cross-attention (fp32, tiny K/V) ----------------
#define XPAD 81
#define XSMEM_FLOATS (2*CN*XPAD + 8*80)

__global__ __launch_bounds__(256)
void cross_attn_kernel(const float* __restrict__ Q, const float* __restrict__ K2,
                       const float* __restrict__ V2, float* __restrict__ O)
{
    extern __shared__ float sm[];
    float* Ks = sm;
    float* Vs = Ks + CN * XPAD;
    float* Ps = Vs + CN * XPAD;

    const int tid = threadIdx.x, lane = tid & 31, w = tid >> 5;
    const int h = blockIdx.y, b = blockIdx.z;
    const float scale = 0.11180339887498949f;

    for (int e = tid; e < CN * 80; e += 256) {
        int n = e / 80, d = e % 80;
        Ks[n * XPAD + d] = K2[(size_t)(b * CN + n) * DD + h * DH + d];
        Vs[n * XPAD + d] = V2[(size_t)(b * CN + n) * DD + h * DH + d];
    }
    __syncthreads();

    const int row0 = blockIdx.x * 64;
    for (int r = w; r < 64; r += 8) {
        const int token = row0 + r;
        const float* qr = Q + ((size_t)b * NN + token) * DD + h * DH;

        const int k0 = lane, k1 = lane + 32, k2 = lane + 64;
        const bool v2ok = (k2 < CN);
        const float* ks0 = &Ks[k0 * XPAD];
        const float* ks1 = &Ks[k1 * XPAD];
        const float* ks2 = &Ks[(v2ok ? k2 : 0) * XPAD];
        float a0 = 0.f, a1 = 0.f, a2 = 0.f;
        #pragma unroll 10
        for (int d = 0; d < 80; d++) {
            float qd = __ldg(qr + d);
            a0 = fmaf(qd, ks0[d], a0);
            a1 = fmaf(qd, ks1[d], a1);
            a2 = fmaf(qd, ks2[d], a2);
        }
        float s0 = a0 * scale, s1 = a1 * scale;
        float s2 = v2ok ? (a2 * scale) : -3.0e38f;

        float mx = fmaxf(fmaxf(s0, s1), s2);
        #pragma unroll
        for (int m = 16; m; m >>= 1) mx = fmaxf(mx, __shfl_xor_sync(0xffffffffu, mx, m));
        float e0 = __expf(s0 - mx), e1 = __expf(s1 - mx);
        float e2 = v2ok ? __expf(s2 - mx) : 0.f;
        float sumv = e0 + e1 + e2;
        #pragma unroll
        for (int m = 16; m; m >>= 1) sumv += __shfl_xor_sync(0xffffffffu, sumv, m);
        float inv = 1.0f / sumv;
        Ps[w * 80 + k0] = e0 * inv;
        Ps[w * 80 + k1] = e1 * inv;
        if (v2ok) Ps[w * 80 + k2] = e2 * inv;
        __syncwarp();

        #pragma unroll
        for (int c = lane; c < 80; c += 32) {
            float oo = 0.f;
            for (int j = 0; j < CN; j++)
                oo = fmaf(Ps[w * 80 + j], Vs[j * XPAD + c], oo);
            O[((size_t)b * NN + token) * DD + h * DH + c] = oo;
        }
        __syncwarp();
    }
}

// ---------------- GEGLU ----------------
__global__ void geglu_kernel(const float* __restrict__ proj, float* __restrict__ out)
{
    int idx = blockIdx.x * blockDim.x + threadIdx.x;
    if (idx >= MROWS * FF) return;
    int row = idx / FF, c = idx % FF;
    float a = proj[(size_t)row * (2 * FF) + c];
    float g = proj[(size_t)row * (2 * FF) + FF + c];
    float gelu = 0.5f * g * (1.0f + erff(g * 0.70710678118654752f));
    out[idx] = a * gelu;
}

// ---------------- host launch ----------------
#define GSMEM128 ((2*128*36 + 2*32*136) * (int)sizeof(float))   // 71680 B
#define GSMEM64  ((2*128*36 + 2*32*72)  * (int)sizeof(float))   // 55296 B

static void launch_gemm(const float* A, const float* W, const float* bias,
                        const float* res, float* C, int M, int K, int Nn)
{
    if (Nn % 128 == 0 && Nn >= 1024) {
        dim3 grid(Nn / 128, (M + 127) / 128);
        mma_gemm_kernel<128><<<grid, 256, GSMEM128>>>(A, W, bias, res, C, M, K, Nn);
    } else {
        dim3 grid(Nn / 64, (M + 127) / 128);
        mma_gemm_kernel<64><<<grid, 256, GSMEM64>>>(A, W, bias, res, C, M, K, Nn);
    }
}

extern "C" void kernel_launch(void* const* d_in, const int* in_sizes, int n_in,
                              void* d_out, int out_size)
{
    (void)in_sizes; (void)n_in; (void)out_size;
    const float* x     = (const float*)d_in[0];
    const float* ctx   = (const float*)d_in[1];
    const float* ln1_w = (const float*)d_in[2];
    const float* ln1_b = (const float*)d_in[3];
    const float* ln2_w = (const float*)d_in[4];
    const float* ln2_b = (const float*)d_in[5];
    const float* ln3_w = (const float*)d_in[6];
    const float* ln3_b = (const float*)d_in[7];
    const float* wq1   = (const float*)d_in[8];
    const float* wk1   = (const float*)d_in[9];
    const float* wv1   = (const float*)d_in[10];
    const float* wo1   = (const float*)d_in[11];
    const float* bo1   = (const float*)d_in[12];
    const float* wq2   = (const float*)d_in[13];
    const float* wk2   = (const float*)d_in[14];
    const float* wv2   = (const float*)d_in[15];
    const float* wo2   = (const float*)d_in[16];
    const float* bo2   = (const float*)d_in[17];
    const float* wff1  = (const float*)d_in[18];
    const float* bff1  = (const float*)d_in[19];
    const float* wff2  = (const float*)d_in[20];
    const float* bff2  = (const float*)d_in[21];
    float* out = (float*)d_out;

    float *h, *q, *k, *v, *attn, *x2, *x3, *proj, *ffin;
    cudaGetSymbolAddress((void**)&h,    g_h);
    cudaGetSymbolAddress((void**)&q,    g_q);
    cudaGetSymbolAddress((void**)&k,    g_k);
    cudaGetSymbolAddress((void**)&v,    g_v);
    cudaGetSymbolAddress((void**)&attn, g_attn);
    cudaGetSymbolAddress((void**)&x2,   g_x2);
    cudaGetSymbolAddress((void**)&x3,   g_x3);
    cudaGetSymbolAddress((void**)&proj, g_proj);
    cudaGetSymbolAddress((void**)&ffin, g_ffin);

    cudaFuncSetAttribute(mma_gemm_kernel<128>, cudaFuncAttributeMaxDynamicSharedMemorySize, GSMEM128);
    cudaFuncSetAttribute(mma_gemm_kernel<64>,  cudaFuncAttributeMaxDynamicSharedMemorySize, GSMEM64);
    cudaFuncSetAttribute(self_attn_tc_kernel, cudaFuncAttributeMaxDynamicSharedMemorySize,
                         ASMEM_FLOATS * (int)sizeof(float));
    cudaFuncSetAttribute(cross_attn_kernel, cudaFuncAttributeMaxDynamicSharedMemorySize,
                         XSMEM_FLOATS * (int)sizeof(float));

    // ---- Block 1: self-attention ----
    ln_kernel<<<MROWS, 256>>>(x, ln1_w, ln1_b, h);
    launch_gemm(h, wq1, nullptr, nullptr, q, MROWS, DD, DD);
    launch_gemm(h, wk1, nullptr, nullptr, k, MROWS, DD, DD);
    launch_gemm(h, wv1, nullptr, nullptr, v, MROWS, DD, DD);
    {
        dim3 grid(NN / 64, HH, BB);
        self_attn_tc_kernel<<<grid, 128, ASMEM_FLOATS * sizeof(float)>>>(q, k, v, attn);
    }
    launch_gemm(attn, wo1, bo1, x, x2, MROWS, DD, DD);

    // ---- Block 2: cross-attention ----
    ln_kernel<<<MROWS, 256>>>(x2, ln2_w, ln2_b, h);
    launch_gemm(h,   wq2, nullptr, nullptr, q, MROWS, DD, DD);
    launch_gemm(ctx, wk2, nullptr, nullptr, k, CROWS, CD, DD);
    launch_gemm(ctx, wv2, nullptr, nullptr, v, CROWS, CD, DD);
    {
        dim3 grid(NN / 64, HH, BB);
        cross_attn_kernel<<<grid, 256, XSMEM_FLOATS * sizeof(float)>>>(q, k, v, attn);
    }
    launch_gemm(attn, wo2, bo2, x2, x3, MROWS, DD, DD);

    // ---- Block 3: GEGLU FFN ----
    ln_kernel<<<MROWS, 256>>>(x3, ln3_w, ln3_b, h);
    launch_gemm(h, wff1, bff1, nullptr, proj, MROWS, DD, 2 * FF);
    {
        int tot = MROWS * FF;
        geglu_kernel<<<(tot + 255) / 256, 256>>>(proj, ffin);
    }
    launch_gemm(ffin, wff2, bff2, x3, out, MROWS, FF, DD);
}